// round 2
// baseline (speedup 1.0000x reference)
#include <cuda_runtime.h>
#include <cstdint>

#define NNODES 100000
#define NEDGES 1600000

// Scratch (device globals — no allocation allowed)
__device__ float g_PSn[NNODES * 128];  // h @ W1[64:128]   (sender projection)
__device__ float g_PRn[NNODES * 128];  // h @ W1[128:192]  (receiver projection)
__device__ float g_Th [NNODES * 64];   // h @ W_node[0:64]
__device__ float g_agg[NNODES * 64];   // scatter accumulator

typedef unsigned long long u64;

// ---- packed f32x2 helpers (Blackwell FFMA2 is PTX-only) ----
__device__ __forceinline__ void fma2(u64 &d, u64 a, u64 b) {
    asm("fma.rn.f32x2 %0, %1, %2, %0;" : "+l"(d) : "l"(a), "l"(b));
}
__device__ __forceinline__ u64 bc2(float x) {
    u64 r; unsigned xi = __float_as_uint(x);
    asm("mov.b64 %0, {%1, %1};" : "=l"(r) : "r"(xi));
    return r;
}
__device__ __forceinline__ float2 unpack2(u64 v) {
    unsigned lo, hi;
    asm("mov.b64 {%0, %1}, %2;" : "=r"(lo), "=r"(hi) : "l"(v));
    float2 f; f.x = __uint_as_float(lo); f.y = __uint_as_float(hi);
    return f;
}

// ============================================================================
// Kernel 1: node precompute. Per 64-node tile computes
//   PSn = h @ W1[64:128]   (128 cols)
//   PRn = h @ W1[128:192]  (128 cols)
//   Th  = h @ W_node[0:64] (64 cols)
// ============================================================================
__global__ void __launch_bounds__(256, 2)
node_pre_kernel(const float* __restrict__ h, const float* __restrict__ W1,
                const float* __restrict__ Wn, int N)
{
    __shared__ float sX[64 * 64];    // node feature tile, row-major
    __shared__ float sW[64 * 128];   // weight tile (reloaded per phase)

    const int t = threadIdx.x;
    const int tx = t & 15, ty = t >> 4;
    const int base = blockIdx.x * 64;
    const int r0 = ty * 4;

    // stage X
    #pragma unroll
    for (int i = 0; i < 4; i++) {
        int q = t + i * 256;            // < 1024
        int r = q >> 4, c4 = q & 15;
        int n = base + r;
        float4 v = make_float4(0.f, 0.f, 0.f, 0.f);
        if (n < N) v = *(const float4*)&h[(size_t)n * 64 + c4 * 4];
        *(float4*)&sX[r * 64 + c4 * 4] = v;
    }

    for (int ph = 0; ph < 3; ph++) {
        const float* Wsrc = (ph == 0) ? (W1 + 64 * 128)
                          : (ph == 1) ? (W1 + 128 * 128)
                          : Wn;
        const int ncol = (ph < 2) ? 128 : 64;
        float* outp = (ph == 0) ? g_PSn : (ph == 1) ? g_PRn : g_Th;

        __syncthreads();   // previous phase done reading sW
        for (int i = t; i < 64 * ncol; i += 256) sW[i] = Wsrc[i];
        __syncthreads();

        if (ncol == 128) {
            const int c0 = tx * 8;
            u64 acc[4][4];
            #pragma unroll
            for (int i = 0; i < 4; i++)
                #pragma unroll
                for (int j = 0; j < 4; j++) acc[i][j] = 0ull;
            #pragma unroll 4
            for (int k = 0; k < 64; k++) {
                float xs[4];
                #pragma unroll
                for (int i = 0; i < 4; i++) xs[i] = sX[(r0 + i) * 64 + k];
                ulonglong2 w0 = *(const ulonglong2*)&sW[k * 128 + c0];
                ulonglong2 w1 = *(const ulonglong2*)&sW[k * 128 + c0 + 4];
                #pragma unroll
                for (int i = 0; i < 4; i++) {
                    u64 xb = bc2(xs[i]);
                    fma2(acc[i][0], xb, w0.x);
                    fma2(acc[i][1], xb, w0.y);
                    fma2(acc[i][2], xb, w1.x);
                    fma2(acc[i][3], xb, w1.y);
                }
            }
            #pragma unroll
            for (int i = 0; i < 4; i++) {
                int n = base + r0 + i;
                if (n < N) {
                    ulonglong2 s0, s1;
                    s0.x = acc[i][0]; s0.y = acc[i][1];
                    s1.x = acc[i][2]; s1.y = acc[i][3];
                    *(ulonglong2*)&outp[(size_t)n * 128 + c0]     = s0;
                    *(ulonglong2*)&outp[(size_t)n * 128 + c0 + 4] = s1;
                }
            }
        } else {
            const int c0 = tx * 4;
            u64 acc[4][2];
            #pragma unroll
            for (int i = 0; i < 4; i++) { acc[i][0] = 0ull; acc[i][1] = 0ull; }
            #pragma unroll 4
            for (int k = 0; k < 64; k++) {
                float xs[4];
                #pragma unroll
                for (int i = 0; i < 4; i++) xs[i] = sX[(r0 + i) * 64 + k];
                ulonglong2 w = *(const ulonglong2*)&sW[k * 64 + c0];
                #pragma unroll
                for (int i = 0; i < 4; i++) {
                    u64 xb = bc2(xs[i]);
                    fma2(acc[i][0], xb, w.x);
                    fma2(acc[i][1], xb, w.y);
                }
            }
            #pragma unroll
            for (int i = 0; i < 4; i++) {
                int n = base + r0 + i;
                if (n < N) {
                    ulonglong2 s; s.x = acc[i][0]; s.y = acc[i][1];
                    *(ulonglong2*)&outp[(size_t)n * 64 + c0] = s;
                }
            }
        }
    }
}

// ============================================================================
// Kernel 2: persistent edge kernel. Per 64-edge tile:
//   H = relu(X @ W1[0:64] + PSn[s] + PRn[r] + b1)        [64 x 128]
//   M = H @ W2 + b2                                       [64 x 64]
//   scatter: agg[rcv] += M   (atomicAdd float4)
//   e_new = relu(X @ We[0:64] + M @ We[64:128] + be)      [64 x 64]
// Weights live in smem for the whole kernel (1 CTA/SM).
// ============================================================================
#define EDGE_SMEM_FLOATS (8192 + 8192 + 4096 + 4096 + 8192 + 4096 + 4096 + 128 + 64 + 64)
#define EDGE_SMEM_BYTES  (EDGE_SMEM_FLOATS * 4 + 128 * 4)

__global__ void __launch_bounds__(256, 1)
edge_kernel(const float* __restrict__ e, const int* __restrict__ snd,
            const int* __restrict__ rcv,
            const float* __restrict__ W1, const float* __restrict__ b1,
            const float* __restrict__ W2, const float* __restrict__ b2,
            const float* __restrict__ We, const float* __restrict__ be,
            float* __restrict__ e_new, int E)
{
    extern __shared__ float sm[];
    float* sW1  = sm;                 // 64*128  W1 rows 0..63
    float* sW2  = sW1 + 64 * 128;     // 128*64
    float* sWee = sW2 + 128 * 64;     // 64*64   W_edge rows 0..63
    float* sWem = sWee + 64 * 64;     // 64*64   W_edge rows 64..127
    float* sU   = sWem + 64 * 64;     // 64*128  PS-sum, then H (relu'd)
    float* sX   = sU + 64 * 128;      // 64*64   edge features
    float* sM   = sX + 64 * 64;       // 64*64   messages
    float* sb1  = sM + 64 * 64;       // 128
    float* sb2  = sb1 + 128;          // 64
    float* sbe  = sb2 + 64;           // 64
    int*   sidxs = (int*)(sbe + 64);  // 64
    int*   sidxr = sidxs + 64;        // 64

    const int t = threadIdx.x;
    const int tx = t & 15, ty = t >> 4;
    const int r0 = ty * 4;
    const int c0 = tx * 8;   // 128-col tiling
    const int c0b = tx * 4;  // 64-col tiling

    // load weights once (persistent CTA)
    for (int i = t; i < 64 * 128; i += 256) sW1[i] = W1[i];
    for (int i = t; i < 128 * 64; i += 256) sW2[i] = W2[i];
    for (int i = t; i < 64 * 64; i += 256) { sWee[i] = We[i]; sWem[i] = We[64 * 64 + i]; }
    if (t < 128) sb1[t] = b1[t];
    if (t < 64) { sb2[t] = b2[t]; sbe[t] = be[t]; }
    __syncthreads();

    const int ntiles = (E + 63) >> 6;

    for (int tile = blockIdx.x; tile < ntiles; tile += gridDim.x) {
        const int base = tile << 6;

        // ---- stage indices + X ----
        if (t < 64) {
            int ei = base + t; if (ei >= E) ei = E - 1;
            sidxs[t] = snd[ei];
            sidxr[t] = rcv[ei];
        }
        #pragma unroll
        for (int i = 0; i < 4; i++) {
            int q = t + i * 256;           // < 1024
            int r = q >> 4, c4 = q & 15;
            int ei = base + r; if (ei >= E) ei = E - 1;
            *(float4*)&sX[r * 64 + c4 * 4] = *(const float4*)&e[(size_t)ei * 64 + c4 * 4];
        }
        __syncthreads();

        // ---- stage PS = PSn[s] + PRn[r] + b1 ----
        #pragma unroll
        for (int i = 0; i < 8; i++) {
            int q = t + i * 256;           // < 2048
            int r = q >> 5, c4 = q & 31;
            int s = sidxs[r], rr = sidxr[r];
            float4 a  = *(const float4*)&g_PSn[(size_t)s  * 128 + c4 * 4];
            float4 b  = *(const float4*)&g_PRn[(size_t)rr * 128 + c4 * 4];
            float4 bb = *(const float4*)&sb1[c4 * 4];
            a.x += b.x + bb.x; a.y += b.y + bb.y;
            a.z += b.z + bb.z; a.w += b.w + bb.w;
            *(float4*)&sU[r * 128 + c4 * 4] = a;
        }
        __syncthreads();

        // ---- GEMM1: acc = PS(+b1), then += X @ W1e ----
        u64 acc[4][4];
        #pragma unroll
        for (int i = 0; i < 4; i++) {
            ulonglong2 p0 = *(const ulonglong2*)&sU[(r0 + i) * 128 + c0];
            ulonglong2 p1 = *(const ulonglong2*)&sU[(r0 + i) * 128 + c0 + 4];
            acc[i][0] = p0.x; acc[i][1] = p0.y; acc[i][2] = p1.x; acc[i][3] = p1.y;
        }
        __syncthreads();   // all init-reads of sU done; safe to overwrite after K-loop
        #pragma unroll 4
        for (int k = 0; k < 64; k++) {
            float xs[4];
            #pragma unroll
            for (int i = 0; i < 4; i++) xs[i] = sX[(r0 + i) * 64 + k];
            ulonglong2 w0 = *(const ulonglong2*)&sW1[k * 128 + c0];
            ulonglong2 w1 = *(const ulonglong2*)&sW1[k * 128 + c0 + 4];
            #pragma unroll
            for (int i = 0; i < 4; i++) {
                u64 xb = bc2(xs[i]);
                fma2(acc[i][0], xb, w0.x);
                fma2(acc[i][1], xb, w0.y);
                fma2(acc[i][2], xb, w1.x);
                fma2(acc[i][3], xb, w1.y);
            }
        }
        // relu + write H back into sU
        #pragma unroll
        for (int i = 0; i < 4; i++) {
            float2 a0 = unpack2(acc[i][0]), a1 = unpack2(acc[i][1]);
            float2 a2 = unpack2(acc[i][2]), a3 = unpack2(acc[i][3]);
            float4 h0 = make_float4(fmaxf(a0.x, 0.f), fmaxf(a0.y, 0.f),
                                    fmaxf(a1.x, 0.f), fmaxf(a1.y, 0.f));
            float4 h1 = make_float4(fmaxf(a2.x, 0.f), fmaxf(a2.y, 0.f),
                                    fmaxf(a3.x, 0.f), fmaxf(a3.y, 0.f));
            *(float4*)&sU[(r0 + i) * 128 + c0]     = h0;
            *(float4*)&sU[(r0 + i) * 128 + c0 + 4] = h1;
        }
        __syncthreads();

        // ---- GEMM2: M = H @ W2 + b2 ----
        u64 m2[4][2];
        {
            ulonglong2 b = *(const ulonglong2*)&sb2[c0b];
            #pragma unroll
            for (int i = 0; i < 4; i++) { m2[i][0] = b.x; m2[i][1] = b.y; }
        }
        #pragma unroll 4
        for (int k = 0; k < 128; k++) {
            float hs[4];
            #pragma unroll
            for (int i = 0; i < 4; i++) hs[i] = sU[(r0 + i) * 128 + k];
            ulonglong2 w = *(const ulonglong2*)&sW2[k * 64 + c0b];
            #pragma unroll
            for (int i = 0; i < 4; i++) {
                u64 xb = bc2(hs[i]);
                fma2(m2[i][0], xb, w.x);
                fma2(m2[i][1], xb, w.y);
            }
        }
        #pragma unroll
        for (int i = 0; i < 4; i++) {
            ulonglong2 s; s.x = m2[i][0]; s.y = m2[i][1];
            *(ulonglong2*)&sM[(r0 + i) * 64 + c0b] = s;
        }
        __syncthreads();

        // ---- scatter messages into agg (issue early, overlap with GEMM3) ----
        #pragma unroll
        for (int i = 0; i < 4; i++) {
            int q = t + i * 256;           // < 1024
            int r = q >> 4, c4 = q & 15;
            int ei = base + r;
            if (ei < E) {
                float4 v = *(const float4*)&sM[r * 64 + c4 * 4];
                atomicAdd((float4*)&g_agg[(size_t)sidxr[r] * 64 + c4 * 4], v);
            }
        }

        // ---- GEMM3: e_new = relu(X @ We_e + M @ We_m + be) ----
        u64 o[4][2];
        {
            ulonglong2 b = *(const ulonglong2*)&sbe[c0b];
            #pragma unroll
            for (int i = 0; i < 4; i++) { o[i][0] = b.x; o[i][1] = b.y; }
        }
        #pragma unroll 4
        for (int k = 0; k < 64; k++) {
            float xs[4];
            #pragma unroll
            for (int i = 0; i < 4; i++) xs[i] = sX[(r0 + i) * 64 + k];
            ulonglong2 w = *(const ulonglong2*)&sWee[k * 64 + c0b];
            #pragma unroll
            for (int i = 0; i < 4; i++) {
                u64 xb = bc2(xs[i]);
                fma2(o[i][0], xb, w.x);
                fma2(o[i][1], xb, w.y);
            }
        }
        #pragma unroll 4
        for (int k = 0; k < 64; k++) {
            float ms[4];
            #pragma unroll
            for (int i = 0; i < 4; i++) ms[i] = sM[(r0 + i) * 64 + k];
            ulonglong2 w = *(const ulonglong2*)&sWem[k * 64 + c0b];
            #pragma unroll
            for (int i = 0; i < 4; i++) {
                u64 xb = bc2(ms[i]);
                fma2(o[i][0], xb, w.x);
                fma2(o[i][1], xb, w.y);
            }
        }
        #pragma unroll
        for (int i = 0; i < 4; i++) {
            int ei = base + r0 + i;
            if (ei < E) {
                float2 a0 = unpack2(o[i][0]), a1 = unpack2(o[i][1]);
                float4 v = make_float4(fmaxf(a0.x, 0.f), fmaxf(a0.y, 0.f),
                                       fmaxf(a1.x, 0.f), fmaxf(a1.y, 0.f));
                *(float4*)&e_new[(size_t)ei * 64 + c0b] = v;
            }
        }
        __syncthreads();   // tile done; safe to restage
    }
}

// ============================================================================
// Kernel 3: node update. h_new = relu(Th + agg @ W_node[64:128] + b_node)
// ============================================================================
__global__ void __launch_bounds__(256, 2)
node_upd_kernel(const float* __restrict__ Wn, const float* __restrict__ bn,
                float* __restrict__ h_new, int N)
{
    __shared__ float sA[64 * 64];
    __shared__ float sW[64 * 64];
    __shared__ float sb[64];

    const int t = threadIdx.x;
    const int tx = t & 15, ty = t >> 4;
    const int base = blockIdx.x * 64;
    const int r0 = ty * 4, c0 = tx * 4;

    #pragma unroll
    for (int i = 0; i < 4; i++) {
        int q = t + i * 256;
        int r = q >> 4, c4 = q & 15;
        int n = base + r;
        float4 v = make_float4(0.f, 0.f, 0.f, 0.f);
        if (n < N) v = *(const float4*)&g_agg[(size_t)n * 64 + c4 * 4];
        *(float4*)&sA[r * 64 + c4 * 4] = v;
    }
    for (int i = t; i < 64 * 64; i += 256) sW[i] = Wn[64 * 64 + i];
    if (t < 64) sb[t] = bn[t];
    __syncthreads();

    u64 acc[4][2];
    #pragma unroll
    for (int i = 0; i < 4; i++) { acc[i][0] = 0ull; acc[i][1] = 0ull; }
    #pragma unroll 4
    for (int k = 0; k < 64; k++) {
        float as[4];
        #pragma unroll
        for (int i = 0; i < 4; i++) as[i] = sA[(r0 + i) * 64 + k];
        ulonglong2 w = *(const ulonglong2*)&sW[k * 64 + c0];
        #pragma unroll
        for (int i = 0; i < 4; i++) {
            u64 xb = bc2(as[i]);
            fma2(acc[i][0], xb, w.x);
            fma2(acc[i][1], xb, w.y);
        }
    }
    #pragma unroll
    for (int i = 0; i < 4; i++) {
        int n = base + r0 + i;
        if (n < N) {
            float4 th = *(const float4*)&g_Th[(size_t)n * 64 + c0];
            float2 a0 = unpack2(acc[i][0]), a1 = unpack2(acc[i][1]);
            float4 v = make_float4(
                fmaxf(a0.x + th.x + sb[c0 + 0], 0.f),
                fmaxf(a0.y + th.y + sb[c0 + 1], 0.f),
                fmaxf(a1.x + th.z + sb[c0 + 2], 0.f),
                fmaxf(a1.y + th.w + sb[c0 + 3], 0.f));
            *(float4*)&h_new[(size_t)n * 64 + c0] = v;
        }
    }
}

// ============================================================================
// Launch
// ============================================================================
extern "C" void kernel_launch(void* const* d_in, const int* in_sizes, int n_in,
                              void* d_out, int out_size)
{
    const float* h  = (const float*)d_in[0];
    const float* e  = (const float*)d_in[1];
    const int* snd  = (const int*)d_in[2];
    const int* rcv  = (const int*)d_in[3];
    const float* W1 = (const float*)d_in[4];
    const float* b1 = (const float*)d_in[5];
    const float* W2 = (const float*)d_in[6];
    const float* b2 = (const float*)d_in[7];
    const float* Wn = (const float*)d_in[8];
    const float* bn = (const float*)d_in[9];
    const float* We = (const float*)d_in[10];
    const float* be = (const float*)d_in[11];

    const int N = in_sizes[0] / 64;
    const int E = in_sizes[2];
    float* h_new = (float*)d_out;
    float* e_new = h_new + (size_t)N * 64;

    void* aggp = nullptr;
    cudaGetSymbolAddress(&aggp, g_agg);
    cudaMemsetAsync(aggp, 0, (size_t)N * 64 * sizeof(float));

    const int nblk = (N + 63) / 64;
    node_pre_kernel<<<nblk, 256>>>(h, W1, Wn, N);

    cudaFuncSetAttribute(edge_kernel, cudaFuncAttributeMaxDynamicSharedMemorySize,
                         EDGE_SMEM_BYTES);
    int nsm = 148;
    cudaDeviceGetAttribute(&nsm, cudaDevAttrMultiProcessorCount, 0);
    edge_kernel<<<nsm, 256, EDGE_SMEM_BYTES>>>(e, snd, rcv, W1, b1, W2, b2,
                                               We, be, e_new, E);

    node_upd_kernel<<<nblk, 256>>>(Wn, bn, h_new, N);
}

// round 5
// speedup vs baseline: 1.0891x; 1.0891x over previous
#include <cuda_runtime.h>
#include <cstdint>

#define NNODES 100000
#define NEDGES 1600000

// Scratch (device globals — no allocation allowed)
__device__ float g_PSn[NNODES * 128];  // h @ W1[64:128]   (sender projection)
__device__ float g_PRn[NNODES * 128];  // h @ W1[128:192]  (receiver projection)
__device__ float g_Th [NNODES * 64];   // h @ W_node[0:64]
__device__ float g_agg[NNODES * 64];   // scatter accumulator

typedef unsigned long long u64;

// ---- packed f32x2 helpers (Blackwell FFMA2 is PTX-only) ----
__device__ __forceinline__ void fma2(u64 &d, u64 a, u64 b) {
    asm("fma.rn.f32x2 %0, %1, %2, %0;" : "+l"(d) : "l"(a), "l"(b));
}
__device__ __forceinline__ u64 bc2(float x) {
    u64 r; unsigned xi = __float_as_uint(x);
    asm("mov.b64 %0, {%1, %1};" : "=l"(r) : "r"(xi));
    return r;
}
__device__ __forceinline__ float2 unpack2(u64 v) {
    unsigned lo, hi;
    asm("mov.b64 {%0, %1}, %2;" : "=r"(lo), "=r"(hi) : "l"(v));
    float2 f; f.x = __uint_as_float(lo); f.y = __uint_as_float(hi);
    return f;
}

// ============================================================================
// Kernel 1: node precompute. Per 64-node tile computes
//   PSn = h @ W1[64:128], PRn = h @ W1[128:192], Th = h @ W_node[0:64]
// ============================================================================
__global__ void __launch_bounds__(256, 2)
node_pre_kernel(const float* __restrict__ h, const float* __restrict__ W1,
                const float* __restrict__ Wn, int N)
{
    __shared__ float sX[64 * 64];
    __shared__ float sW[64 * 128];

    const int t = threadIdx.x;
    const int tx = t & 15, ty = t >> 4;
    const int base = blockIdx.x * 64;
    const int r0 = ty * 4;

    #pragma unroll
    for (int i = 0; i < 4; i++) {
        int q = t + i * 256;
        int r = q >> 4, c4 = q & 15;
        int n = base + r;
        float4 v = make_float4(0.f, 0.f, 0.f, 0.f);
        if (n < N) v = *(const float4*)&h[(size_t)n * 64 + c4 * 4];
        *(float4*)&sX[r * 64 + c4 * 4] = v;
    }

    for (int ph = 0; ph < 3; ph++) {
        const float* Wsrc = (ph == 0) ? (W1 + 64 * 128)
                          : (ph == 1) ? (W1 + 128 * 128)
                          : Wn;
        const int ncol = (ph < 2) ? 128 : 64;
        float* outp = (ph == 0) ? g_PSn : (ph == 1) ? g_PRn : g_Th;

        __syncthreads();
        for (int i = t; i < 64 * ncol; i += 256) sW[i] = Wsrc[i];
        __syncthreads();

        if (ncol == 128) {
            const int c0 = tx * 8;
            u64 acc[4][4];
            #pragma unroll
            for (int i = 0; i < 4; i++)
                #pragma unroll
                for (int j = 0; j < 4; j++) acc[i][j] = 0ull;
            #pragma unroll 4
            for (int k = 0; k < 64; k++) {
                float xs[4];
                #pragma unroll
                for (int i = 0; i < 4; i++) xs[i] = sX[(r0 + i) * 64 + k];
                ulonglong2 w0 = *(const ulonglong2*)&sW[k * 128 + c0];
                ulonglong2 w1 = *(const ulonglong2*)&sW[k * 128 + c0 + 4];
                #pragma unroll
                for (int i = 0; i < 4; i++) {
                    u64 xb = bc2(xs[i]);
                    fma2(acc[i][0], xb, w0.x);
                    fma2(acc[i][1], xb, w0.y);
                    fma2(acc[i][2], xb, w1.x);
                    fma2(acc[i][3], xb, w1.y);
                }
            }
            #pragma unroll
            for (int i = 0; i < 4; i++) {
                int n = base + r0 + i;
                if (n < N) {
                    ulonglong2 s0, s1;
                    s0.x = acc[i][0]; s0.y = acc[i][1];
                    s1.x = acc[i][2]; s1.y = acc[i][3];
                    *(ulonglong2*)&outp[(size_t)n * 128 + c0]     = s0;
                    *(ulonglong2*)&outp[(size_t)n * 128 + c0 + 4] = s1;
                }
            }
        } else {
            const int c0 = tx * 4;
            u64 acc[4][2];
            #pragma unroll
            for (int i = 0; i < 4; i++) { acc[i][0] = 0ull; acc[i][1] = 0ull; }
            #pragma unroll 4
            for (int k = 0; k < 64; k++) {
                float xs[4];
                #pragma unroll
                for (int i = 0; i < 4; i++) xs[i] = sX[(r0 + i) * 64 + k];
                ulonglong2 w = *(const ulonglong2*)&sW[k * 64 + c0];
                #pragma unroll
                for (int i = 0; i < 4; i++) {
                    u64 xb = bc2(xs[i]);
                    fma2(acc[i][0], xb, w.x);
                    fma2(acc[i][1], xb, w.y);
                }
            }
            #pragma unroll
            for (int i = 0; i < 4; i++) {
                int n = base + r0 + i;
                if (n < N) {
                    ulonglong2 s; s.x = acc[i][0]; s.y = acc[i][1];
                    *(ulonglong2*)&outp[(size_t)n * 64 + c0] = s;
                }
            }
        }
    }
}

// ============================================================================
// Kernel 2: persistent edge kernel, 128-edge tiles, 8x8 register blocking.
//   H = relu(X @ W1[0:64] + PSn[s] + PRn[r] + b1)        [128 x 128]
//   M = H @ W2 + b2                                       [128 x 64]
//   scatter: agg[rcv] += M   (register-sourced atomicAdd float4)
//   e_new = relu(X @ We[0:64] + M @ We[64:128] + be)      [128 x 64]
// Weights persist in smem; M reuses the H buffer.
// ============================================================================
#define TILE 128
// floats: W1 8192 + W2 8192 + Wee 4096 + Wem 4096 + U 16384 + X 8192 = 49152
// + b1 128 + b2 64 + be 64 + 2*128 ints
#define EDGE_SMEM_BYTES ((49152 + 128 + 64 + 64) * 4 + 2 * 128 * 4 + 128)

__global__ void __launch_bounds__(256, 1)
edge_kernel(const float* __restrict__ e, const int* __restrict__ snd,
            const int* __restrict__ rcv,
            const float* __restrict__ W1, const float* __restrict__ b1,
            const float* __restrict__ W2, const float* __restrict__ b2,
            const float* __restrict__ We, const float* __restrict__ be,
            float* __restrict__ e_new, int E)
{
    extern __shared__ float sm[];
    float* sW1  = sm;                  // 64*128
    float* sW2  = sW1 + 64 * 128;      // 128*64
    float* sWee = sW2 + 128 * 64;      // 64*64
    float* sWem = sWee + 64 * 64;      // 64*64
    float* sU   = sWem + 64 * 64;      // 128*128  (PS-sum -> H -> M)
    float* sX   = sU + 128 * 128;      // 128*64
    float* sb1  = sX + 128 * 64;       // 128
    float* sb2  = sb1 + 128;           // 64
    float* sbe  = sb2 + 64;            // 64
    int*   sidxs = (int*)(sbe + 64);   // 128
    int*   sidxr = sidxs + 128;        // 128

    const int t = threadIdx.x;
    const int tx = t & 15, ty = t >> 4;
    const int r0 = ty * 8;            // 16 row groups x 8 rows = 128 rows
    const int c0 = tx * 8;            // 128-col tiling
    const int c0b = tx * 4;           // 64-col tiling

    // load weights once (persistent CTA)
    for (int i = t; i < 64 * 128; i += 256) sW1[i] = W1[i];
    for (int i = t; i < 128 * 64; i += 256) sW2[i] = W2[i];
    for (int i = t; i < 64 * 64; i += 256) { sWee[i] = We[i]; sWem[i] = We[64 * 64 + i]; }
    if (t < 128) sb1[t] = b1[t];
    if (t < 64) { sb2[t] = b2[t]; sbe[t] = be[t]; }
    __syncthreads();

    const int ntiles = (E + TILE - 1) / TILE;

    for (int tile = blockIdx.x; tile < ntiles; tile += gridDim.x) {
        const int base = tile * TILE;

        // ---- stage indices + X ----
        if (t < 128) {
            int ei = base + t; if (ei >= E) ei = E - 1;
            sidxs[t] = snd[ei];
            sidxr[t] = rcv[ei];
        }
        #pragma unroll
        for (int i = 0; i < 8; i++) {
            int q = t + i * 256;              // < 2048
            int r = q >> 4, c4 = q & 15;
            int ei = base + r; if (ei >= E) ei = E - 1;
            *(float4*)&sX[r * 64 + c4 * 4] = *(const float4*)&e[(size_t)ei * 64 + c4 * 4];
        }
        __syncthreads();

        // ---- stage PS = PSn[s] + PRn[r] + b1 into sU ----
        #pragma unroll
        for (int i = 0; i < 16; i++) {
            int q = t + i * 256;              // < 4096
            int r = q >> 5, c4 = q & 31;
            int s = sidxs[r], rr = sidxr[r];
            float4 a  = *(const float4*)&g_PSn[(size_t)s  * 128 + c4 * 4];
            float4 b  = *(const float4*)&g_PRn[(size_t)rr * 128 + c4 * 4];
            float4 bb = *(const float4*)&sb1[c4 * 4];
            a.x += b.x + bb.x; a.y += b.y + bb.y;
            a.z += b.z + bb.z; a.w += b.w + bb.w;
            *(float4*)&sU[r * 128 + c4 * 4] = a;
        }
        __syncthreads();

        // ---- GEMM1: acc = PS, then += X @ W1e (8 rows x 8 cols/thread) ----
        u64 acc[8][4];
        #pragma unroll
        for (int i = 0; i < 8; i++) {
            ulonglong2 p0 = *(const ulonglong2*)&sU[(r0 + i) * 128 + c0];
            ulonglong2 p1 = *(const ulonglong2*)&sU[(r0 + i) * 128 + c0 + 4];
            acc[i][0] = p0.x; acc[i][1] = p0.y; acc[i][2] = p1.x; acc[i][3] = p1.y;
        }
        __syncthreads();   // init reads done; sU writable after K-loop
        #pragma unroll 2
        for (int k = 0; k < 64; k++) {
            ulonglong2 w0 = *(const ulonglong2*)&sW1[k * 128 + c0];
            ulonglong2 w1 = *(const ulonglong2*)&sW1[k * 128 + c0 + 4];
            float xs[8];
            #pragma unroll
            for (int i = 0; i < 8; i++) xs[i] = sX[(r0 + i) * 64 + k];
            #pragma unroll
            for (int i = 0; i < 8; i++) {
                u64 xb = bc2(xs[i]);
                fma2(acc[i][0], xb, w0.x);
                fma2(acc[i][1], xb, w0.y);
                fma2(acc[i][2], xb, w1.x);
                fma2(acc[i][3], xb, w1.y);
            }
        }
        // relu + write H into sU
        #pragma unroll
        for (int i = 0; i < 8; i++) {
            float2 a0 = unpack2(acc[i][0]), a1 = unpack2(acc[i][1]);
            float2 a2 = unpack2(acc[i][2]), a3 = unpack2(acc[i][3]);
            float4 h0 = make_float4(fmaxf(a0.x, 0.f), fmaxf(a0.y, 0.f),
                                    fmaxf(a1.x, 0.f), fmaxf(a1.y, 0.f));
            float4 h1 = make_float4(fmaxf(a2.x, 0.f), fmaxf(a2.y, 0.f),
                                    fmaxf(a3.x, 0.f), fmaxf(a3.y, 0.f));
            *(float4*)&sU[(r0 + i) * 128 + c0]     = h0;
            *(float4*)&sU[(r0 + i) * 128 + c0 + 4] = h1;
        }
        __syncthreads();

        // ---- GEMM2: M = H @ W2 + b2 (8 rows x 4 cols/thread) ----
        u64 m2[8][2];
        {
            ulonglong2 b = *(const ulonglong2*)&sb2[c0b];
            #pragma unroll
            for (int i = 0; i < 8; i++) { m2[i][0] = b.x; m2[i][1] = b.y; }
        }
        #pragma unroll 2
        for (int k = 0; k < 128; k++) {
            ulonglong2 w = *(const ulonglong2*)&sW2[k * 64 + c0b];
            float hs[8];
            #pragma unroll
            for (int i = 0; i < 8; i++) hs[i] = sU[(r0 + i) * 128 + k];
            #pragma unroll
            for (int i = 0; i < 8; i++) {
                u64 xb = bc2(hs[i]);
                fma2(m2[i][0], xb, w.x);
                fma2(m2[i][1], xb, w.y);
            }
        }
        __syncthreads();   // all H reads done; sU now reusable for M

        // write M into sU (rows 0..127, 64 cols) + register-sourced scatter
        #pragma unroll
        for (int i = 0; i < 8; i++) {
            ulonglong2 s; s.x = m2[i][0]; s.y = m2[i][1];
            *(ulonglong2*)&sU[(r0 + i) * 64 + c0b] = s;
            int ei = base + r0 + i;
            if (ei < E) {
                float2 a0 = unpack2(m2[i][0]), a1 = unpack2(m2[i][1]);
                float4 v = make_float4(a0.x, a0.y, a1.x, a1.y);
                atomicAdd((float4*)&g_agg[(size_t)sidxr[r0 + i] * 64 + c0b], v);
            }
        }
        __syncthreads();

        // ---- GEMM3: e_new = relu(X @ We_e + M @ We_m + be) ----
        u64 o[8][2];
        {
            ulonglong2 b = *(const ulonglong2*)&sbe[c0b];
            #pragma unroll
            for (int i = 0; i < 8; i++) { o[i][0] = b.x; o[i][1] = b.y; }
        }
        #pragma unroll 2
        for (int k = 0; k < 64; k++) {
            ulonglong2 w = *(const ulonglong2*)&sWee[k * 64 + c0b];
            float xs[8];
            #pragma unroll
            for (int i = 0; i < 8; i++) xs[i] = sX[(r0 + i) * 64 + k];
            #pragma unroll
            for (int i = 0; i < 8; i++) {
                u64 xb = bc2(xs[i]);
                fma2(o[i][0], xb, w.x);
                fma2(o[i][1], xb, w.y);
            }
        }
        #pragma unroll 2
        for (int k = 0; k < 64; k++) {
            ulonglong2 w = *(const ulonglong2*)&sWem[k * 64 + c0b];
            float ms[8];
            #pragma unroll
            for (int i = 0; i < 8; i++) ms[i] = sU[(r0 + i) * 64 + k];
            #pragma unroll
            for (int i = 0; i < 8; i++) {
                u64 xb = bc2(ms[i]);
                fma2(o[i][0], xb, w.x);
                fma2(o[i][1], xb, w.y);
            }
        }
        #pragma unroll
        for (int i = 0; i < 8; i++) {
            int ei = base + r0 + i;
            if (ei < E) {
                float2 a0 = unpack2(o[i][0]), a1 = unpack2(o[i][1]);
                float4 v = make_float4(fmaxf(a0.x, 0.f), fmaxf(a0.y, 0.f),
                                       fmaxf(a1.x, 0.f), fmaxf(a1.y, 0.f));
                *(float4*)&e_new[(size_t)ei * 64 + c0b] = v;
            }
        }
        __syncthreads();   // tile done; safe to restage
    }
}

// ============================================================================
// Kernel 3: node update. h_new = relu(Th + agg @ W_node[64:128] + b_node)
// ============================================================================
__global__ void __launch_bounds__(256, 2)
node_upd_kernel(const float* __restrict__ Wn, const float* __restrict__ bn,
                float* __restrict__ h_new, int N)
{
    __shared__ float sA[64 * 64];
    __shared__ float sW[64 * 64];
    __shared__ float sb[64];

    const int t = threadIdx.x;
    const int tx = t & 15, ty = t >> 4;
    const int base = blockIdx.x * 64;
    const int r0 = ty * 4, c0 = tx * 4;

    #pragma unroll
    for (int i = 0; i < 4; i++) {
        int q = t + i * 256;
        int r = q >> 4, c4 = q & 15;
        int n = base + r;
        float4 v = make_float4(0.f, 0.f, 0.f, 0.f);
        if (n < N) v = *(const float4*)&g_agg[(size_t)n * 64 + c4 * 4];
        *(float4*)&sA[r * 64 + c4 * 4] = v;
    }
    for (int i = t; i < 64 * 64; i += 256) sW[i] = Wn[64 * 64 + i];
    if (t < 64) sb[t] = bn[t];
    __syncthreads();

    u64 acc[4][2];
    #pragma unroll
    for (int i = 0; i < 4; i++) { acc[i][0] = 0ull; acc[i][1] = 0ull; }
    #pragma unroll 4
    for (int k = 0; k < 64; k++) {
        float as[4];
        #pragma unroll
        for (int i = 0; i < 4; i++) as[i] = sA[(r0 + i) * 64 + k];
        ulonglong2 w = *(const ulonglong2*)&sW[k * 64 + c0];
        #pragma unroll
        for (int i = 0; i < 4; i++) {
            u64 xb = bc2(as[i]);
            fma2(acc[i][0], xb, w.x);
            fma2(acc[i][1], xb, w.y);
        }
    }
    #pragma unroll
    for (int i = 0; i < 4; i++) {
        int n = base + r0 + i;
        if (n < N) {
            float4 th = *(const float4*)&g_Th[(size_t)n * 64 + c0];
            float2 a0 = unpack2(acc[i][0]), a1 = unpack2(acc[i][1]);
            float4 v = make_float4(
                fmaxf(a0.x + th.x + sb[c0 + 0], 0.f),
                fmaxf(a0.y + th.y + sb[c0 + 1], 0.f),
                fmaxf(a1.x + th.z + sb[c0 + 2], 0.f),
                fmaxf(a1.y + th.w + sb[c0 + 3], 0.f));
            *(float4*)&h_new[(size_t)n * 64 + c0] = v;
        }
    }
}

// ============================================================================
// Launch
// ============================================================================
extern "C" void kernel_launch(void* const* d_in, const int* in_sizes, int n_in,
                              void* d_out, int out_size)
{
    const float* h  = (const float*)d_in[0];
    const float* e  = (const float*)d_in[1];
    const int* snd  = (const int*)d_in[2];
    const int* rcv  = (const int*)d_in[3];
    const float* W1 = (const float*)d_in[4];
    const float* b1 = (const float*)d_in[5];
    const float* W2 = (const float*)d_in[6];
    const float* b2 = (const float*)d_in[7];
    const float* Wn = (const float*)d_in[8];
    const float* bn = (const float*)d_in[9];
    const float* We = (const float*)d_in[10];
    const float* be = (const float*)d_in[11];

    const int N = in_sizes[0] / 64;
    const int E = in_sizes[2];
    float* h_new = (float*)d_out;
    float* e_new = h_new + (size_t)N * 64;

    void* aggp = nullptr;
    cudaGetSymbolAddress(&aggp, g_agg);
    cudaMemsetAsync(aggp, 0, (size_t)N * 64 * sizeof(float));

    const int nblk = (N + 63) / 64;
    node_pre_kernel<<<nblk, 256>>>(h, W1, Wn, N);

    cudaFuncSetAttribute(edge_kernel, cudaFuncAttributeMaxDynamicSharedMemorySize,
                         EDGE_SMEM_BYTES);
    int nsm = 148;
    cudaDeviceGetAttribute(&nsm, cudaDevAttrMultiProcessorCount, 0);
    edge_kernel<<<nsm, 256, EDGE_SMEM_BYTES>>>(e, snd, rcv, W1, b1, W2, b2,
                                               We, be, e_new, E);

    node_upd_kernel<<<nblk, 256>>>(Wn, bn, h_new, N);
}